// round 2
// baseline (speedup 1.0000x reference)
#include <cuda_runtime.h>
#include <float.h>

// Shapes (fixed by the problem): B=32, S=4096, H=1024, K=2
#define B_ 32
#define S_ 4096
#define H_ 1024
#define K_ 2

#define THREADS 128          // threads per block
#define VEC 4                // float4 per thread
#define CHUNK (THREADS*VEC)  // 512 features per block
#define CHUNKS (H_/CHUNK)    // 2

__device__ __forceinline__ float4 f4max(float4 a, float4 b) {
    float4 r;
    r.x = fmaxf(a.x, b.x);
    r.y = fmaxf(a.y, b.y);
    r.z = fmaxf(a.z, b.z);
    r.w = fmaxf(a.w, b.w);
    return r;
}

__global__ void __launch_bounds__(THREADS)
span_max_kernel(const float* __restrict__ hs,   // [B, S, H]
                const int* __restrict__ st,     // [B, K]  (int32 — JAX x64 disabled)
                const int* __restrict__ en,     // [B, K]
                const float* __restrict__ me,   // [K, H]
                float* __restrict__ out)        // [B, K*H]
{
    const int blk   = blockIdx.x;
    const int chunk = blk % CHUNKS;
    const int bk    = blk / CHUNKS;
    const int b     = bk / K_;
    const int k     = bk % K_;

    const int f = chunk * CHUNK + threadIdx.x * VEC;   // feature offset

    const int s_raw = st[b * K_ + k];
    const int e_raw = en[b * K_ + k];

    float* op = out + (size_t)b * (K_ * H_) + (size_t)k * H_ + f;

    if (s_raw < 0 || e_raw < 0) {
        // missing: copy missing_embeddings[k]
        float4 v = *reinterpret_cast<const float4*>(me + (size_t)k * H_ + f);
        *reinterpret_cast<float4*>(op) = v;
        return;
    }

    // defensive clamp: never index outside [0, S)
    int s = s_raw < S_ ? s_raw : S_;
    int e = e_raw < S_ ? e_raw : S_;

    const float* base = hs + ((size_t)b * S_) * H_ + f;

    float4 m = make_float4(-FLT_MAX, -FLT_MAX, -FLT_MAX, -FLT_MAX);

    int r = s;
    // unroll x4: 4 independent 16B loads in flight per thread
    for (; r + 4 <= e; r += 4) {
        float4 a0 = *reinterpret_cast<const float4*>(base + (size_t)(r + 0) * H_);
        float4 a1 = *reinterpret_cast<const float4*>(base + (size_t)(r + 1) * H_);
        float4 a2 = *reinterpret_cast<const float4*>(base + (size_t)(r + 2) * H_);
        float4 a3 = *reinterpret_cast<const float4*>(base + (size_t)(r + 3) * H_);
        m = f4max(m, f4max(f4max(a0, a1), f4max(a2, a3)));
    }
    for (; r < e; ++r) {
        float4 a0 = *reinterpret_cast<const float4*>(base + (size_t)r * H_);
        m = f4max(m, a0);
    }

    *reinterpret_cast<float4*>(op) = m;
}

extern "C" void kernel_launch(void* const* d_in, const int* in_sizes, int n_in,
                              void* d_out, int out_size) {
    const float* hs  = (const float*)d_in[0];
    const int*   st  = (const int*)d_in[1];
    const int*   en  = (const int*)d_in[2];
    const float* me  = (const float*)d_in[3];
    float*       out = (float*)d_out;

    dim3 grid(B_ * K_ * CHUNKS);   // 128 blocks
    span_max_kernel<<<grid, THREADS>>>(hs, st, en, me, out);
}

// round 3
// speedup vs baseline: 1.3478x; 1.3478x over previous
#include <cuda_runtime.h>
#include <float.h>

// Shapes (fixed by the problem): B=32, S=4096, H=1024, K=2
#define B_ 32
#define S_ 4096
#define H_ 1024
#define K_ 2

#define LANES   64                 // feature lanes per block (float4 each)
#define GROUPS  16                 // row groups per block
#define THREADS (LANES*GROUPS)     // 1024
#define CHUNK   (LANES*4)          // 256 features per block
#define CHUNKS  (H_/CHUNK)         // 4
#define MAXSPAN 64                 // length < 64 by construction

__device__ __forceinline__ float4 f4max(float4 a, float4 b) {
    float4 r;
    r.x = fmaxf(a.x, b.x);
    r.y = fmaxf(a.y, b.y);
    r.z = fmaxf(a.z, b.z);
    r.w = fmaxf(a.w, b.w);
    return r;
}

__global__ void __launch_bounds__(THREADS)
span_max_kernel(const float* __restrict__ hs,   // [B, S, H]
                const int* __restrict__ st,     // [B, K] (int32)
                const int* __restrict__ en,     // [B, K]
                const float* __restrict__ me,   // [K, H]
                float* __restrict__ out)        // [B, K*H]
{
    __shared__ float4 part[GROUPS][LANES];

    const int blk   = blockIdx.x;
    const int chunk = blk % CHUNKS;
    const int bk    = blk / CHUNKS;
    const int b     = bk / K_;
    const int k     = bk % K_;

    const int lane = threadIdx.x & (LANES - 1);
    const int g    = threadIdx.x / LANES;

    const int f = chunk * CHUNK + lane * 4;     // feature offset

    const int s_raw = __ldg(&st[b * K_ + k]);
    const int e_raw = __ldg(&en[b * K_ + k]);

    float* op = out + (size_t)b * (K_ * H_) + (size_t)k * H_ + f;

    if (s_raw < 0 || e_raw < 0) {
        // missing: copy missing_embeddings[k]; all threads return (no syncs follow)
        if (g == 0) {
            float4 v = *reinterpret_cast<const float4*>(me + (size_t)k * H_ + f);
            *reinterpret_cast<float4*>(op) = v;
        }
        return;
    }

    // defensive clamps: never index outside [0, S)
    const int s = s_raw < S_ ? s_raw : S_;
    const int e = e_raw < S_ ? e_raw : S_;

    const float* base = hs + ((size_t)b * S_) * H_ + f;

    const float4 NEG = make_float4(-FLT_MAX, -FLT_MAX, -FLT_MAX, -FLT_MAX);
    float4 m = NEG;

    // up to ceil(63/16)=4 rows per thread, fully peeled into independent
    // predicated loads: one latency wait instead of a serial chain.
    const int r0 = s + g;
    const int r1 = r0 + GROUPS;
    const int r2 = r0 + 2 * GROUPS;
    const int r3 = r0 + 3 * GROUPS;

    float4 a0 = (r0 < e) ? *reinterpret_cast<const float4*>(base + (size_t)r0 * H_) : NEG;
    float4 a1 = (r1 < e) ? *reinterpret_cast<const float4*>(base + (size_t)r1 * H_) : NEG;
    float4 a2 = (r2 < e) ? *reinterpret_cast<const float4*>(base + (size_t)r2 * H_) : NEG;
    float4 a3 = (r3 < e) ? *reinterpret_cast<const float4*>(base + (size_t)r3 * H_) : NEG;
    m = f4max(f4max(a0, a1), f4max(a2, a3));

    // tail safety for spans longer than 4*GROUPS (cannot happen with len<64,
    // but keeps the kernel correct for any input)
    for (int r = r0 + 4 * GROUPS; r < e; r += GROUPS) {
        float4 a = *reinterpret_cast<const float4*>(base + (size_t)r * H_);
        m = f4max(m, a);
    }

    part[g][lane] = m;
    __syncthreads();

    if (g == 0) {
        float4 acc = part[0][lane];
        #pragma unroll
        for (int i = 1; i < GROUPS; i++)
            acc = f4max(acc, part[i][lane]);
        *reinterpret_cast<float4*>(op) = acc;
    }
}

extern "C" void kernel_launch(void* const* d_in, const int* in_sizes, int n_in,
                              void* d_out, int out_size) {
    const float* hs  = (const float*)d_in[0];
    const int*   st  = (const int*)d_in[1];
    const int*   en  = (const int*)d_in[2];
    const float* me  = (const float*)d_in[3];
    float*       out = (float*)d_out;

    dim3 grid(B_ * K_ * CHUNKS);   // 256 blocks
    span_max_kernel<<<grid, THREADS>>>(hs, st, en, me, out);
}